// round 12
// baseline (speedup 1.0000x reference)
#include <cuda_runtime.h>
#include <cstdint>

#define NB 2048
#define NT 100
#define ND 128
#define NH 256
#define NW 256
#define KCAT 384
#define KSP 1152           // 3 * KCAT  (3xTF32)
#define NIT 72             // KSP / 16
#define NEG_FILLF (-1.0e9f)
#define PROB_MINF (1e-9f)
#define SMEM_DYN 67584     // max(2*2*[128][20]*4 = 40960, [128][132]*4 = 67584)

// ---------------- static device scratch ----------------
__device__ float g_Benc[1024 * KSP];   // [n][k'] : [Whi | Wlo | Whi]
__device__ float g_Bdec[1024 * KSP];
__device__ float g_benc[1024], g_bdec[1024];
__device__ float g_W1t[NH * NW], g_W2t[NH * NW];
__device__ float g_thi[(size_t)NB * NT * ND];
__device__ float g_tlo[(size_t)NB * NT * ND];
__device__ float g_ehiA[NB * NH], g_eloA[NB * NH], g_ehiB[NB * NH], g_eloB[NB * NH];
__device__ float g_ce[NB * NH];
__device__ float g_dhiA[NB * NH], g_dloA[NB * NH], g_dhiB[NB * NH], g_dloB[NB * NH];
__device__ float g_cd[NB * NH];
__device__ float g_hdfull[NB * NH];
__device__ float g_dinhi[NB * ND], g_dinlo[NB * ND];
__device__ float g_enc[(size_t)NB * NT * NH];
__device__ float g_blend1[(size_t)NB * NT * NW];
__device__ float g_blend2[NB * NW];
__device__ int   g_mask[NB * NT];

// ---------------- helpers ----------------
__device__ __forceinline__ float fast_sigmoid(float x) {
    return __fdividef(1.f, 1.f + __expf(-x));
}
__device__ __forceinline__ float fast_tanh(float x) {
    return 2.f * __fdividef(1.f, 1.f + __expf(-2.f * x)) - 1.f;
}
__device__ __forceinline__ float to_tf32(float x) {
    uint32_t u; asm("cvt.rna.tf32.f32 %0, %1;" : "=r"(u) : "f"(x));
    return __uint_as_float(u);
}
__device__ __forceinline__ uint32_t smem_u32(const void* p) {
    uint32_t a;
    asm("{ .reg .u64 t; cvta.to.shared.u64 t, %1; cvt.u32.u64 %0, t; }" : "=r"(a) : "l"(p));
    return a;
}
#define CP16(dst, src) asm volatile("cp.async.cg.shared.global [%0], [%1], 16;" \
                                    :: "r"(dst), "l"(src) : "memory")
#define CP_COMMIT() asm volatile("cp.async.commit_group;" ::: "memory")
#define CP_WAIT1() asm volatile("cp.async.wait_group 1;" ::: "memory")
#define CP_WAIT0() asm volatile("cp.async.wait_group 0;" ::: "memory")

// ---------------- init ----------------
__global__ void init_kernel(const float* __restrict__ h0, const float* __restrict__ c0) {
    int i = blockIdx.x * blockDim.x + threadIdx.x;   // NB*NH
    g_ehiA[i] = 0.f; g_eloA[i] = 0.f; g_ce[i] = 0.f;
    float v = h0[i], hv = to_tf32(v);
    g_dhiA[i] = hv; g_dloA[i] = to_tf32(v - hv);
    g_cd[i] = c0[i];
    if (i < NB * ND) { g_dinhi[i] = 0.f; g_dinlo[i] = 0.f; }
    if (i < NB * NT) g_mask[i] = 0;
}

__global__ void split_targets_kernel(const float* __restrict__ tg) {
    size_t i = (size_t)blockIdx.x * blockDim.x + threadIdx.x;   // NB*NT*ND
    float v = tg[i], hv = to_tf32(v);
    g_thi[i] = hv; g_tlo[i] = to_tf32(v - hv);
}

// ---------------- prep: split + reorder weights into B' [n][1152] ----------------
__global__ void prep_kernel(const float* __restrict__ ewih, const float* __restrict__ ewhh,
                            const float* __restrict__ ebih, const float* __restrict__ ebhh,
                            const float* __restrict__ dwih, const float* __restrict__ dwhh,
                            const float* __restrict__ dbih, const float* __restrict__ dbhh,
                            const float* __restrict__ W1,   const float* __restrict__ W2) {
    int idx = blockIdx.x * blockDim.x + threadIdx.x;   // 1024*384
    int n = idx / KCAT, k = idx % KCAT;
    int j = n >> 2, g = n & 3, sr = g * NH + j;        // PyTorch gate-major row
    float ve = (k < ND) ? ewih[sr * ND + k] : ewhh[sr * NH + (k - ND)];
    float vd = (k < ND) ? dwih[sr * ND + k] : dwhh[sr * NH + (k - ND)];
    float ehv = to_tf32(ve), elv = to_tf32(ve - ehv);
    float dhv = to_tf32(vd), dlv = to_tf32(vd - dhv);
    size_t base = (size_t)n * KSP + k;
    g_Benc[base] = ehv; g_Benc[base + 384] = elv; g_Benc[base + 768] = ehv;
    g_Bdec[base] = dhv; g_Bdec[base + 384] = dlv; g_Bdec[base + 768] = dhv;
    if (idx < NH * NW) {
        int kk = idx >> 8, w = idx & 255;
        g_W1t[idx] = W1[w * NH + kk];
        g_W2t[idx] = W2[w * NH + kk];
    }
    if (idx < 1024) {
        // FIX: recompute gate-major row for the bias layout col = j*4+g
        int jb = idx >> 2, gb = idx & 3, srb = gb * NH + jb;
        g_benc[idx] = ebih[srb] + ebhh[srb];
        g_bdec[idx] = dbih[srb] + dbhh[srb];
    }
}

// ---------------- 3xTF32 mma.sync LSTM step (GEMM + fused cell epilogue) ----------------
// C[2048,1024] = A'[2048,1152] @ B'[1152,1024]; A' = [xhi|hhi  xhi|hhi  xlo|hlo] per 384-block.
// CTA tile 128x128, 8 warps of 32x64, k16 double-buffered cp.async chunks.
__global__ __launch_bounds__(256) void gemm_lstm_mma(int t, int is_dec) {
    extern __shared__ float sm[];
    const int tid = threadIdx.x;
    const int rb0 = blockIdx.y * 128;
    const int nb0 = blockIdx.x * 128;
    const int j0 = nb0 >> 2;

    const float *Xhi, *Xlo, *Hhi, *Hlo, *Bmat, *bias;
    float *HhiO, *HloO, *Cst, *HfullO;
    size_t xs; int xoff;
    if (is_dec) {
        Xhi = g_dinhi; Xlo = g_dinlo; xs = ND; xoff = 0;
        Hhi = (t & 1) ? g_dhiB : g_dhiA;  Hlo = (t & 1) ? g_dloB : g_dloA;
        HhiO = (t & 1) ? g_dhiA : g_dhiB; HloO = (t & 1) ? g_dloA : g_dloB;
        Cst = g_cd; Bmat = g_Bdec; bias = g_bdec; HfullO = g_hdfull;
    } else {
        Xhi = g_thi; Xlo = g_tlo; xs = (size_t)NT * ND; xoff = t * ND;
        Hhi = (t & 1) ? g_ehiB : g_ehiA;  Hlo = (t & 1) ? g_eloB : g_eloA;
        HhiO = (t & 1) ? g_ehiA : g_ehiB; HloO = (t & 1) ? g_eloA : g_eloB;
        Cst = g_ce; Bmat = g_Benc; bias = g_benc; HfullO = nullptr;
    }

    float* As = sm;          // [2][128][20]
    float* Bs = sm + 5120;   // [2][128][20]
    const uint32_t Au = smem_u32(sm);
    const uint32_t Bu = Au + 5120u * 4u;

    auto load_chunk = [&](int it) {
        int kp = it * 16;
        int term = kp / 384;                 // 0: hi.Whi  1: hi.Wlo  2: lo.Whi
        int k = kp - term * 384;
        bool lo = (term == 2);
        const float* P; size_t stride; int off;
        if (k < ND) { P = lo ? Xlo : Xhi; stride = xs; off = xoff + k; }
        else        { P = lo ? Hlo : Hhi; stride = NH; off = k - ND; }
        uint32_t Ad = Au + (uint32_t)(it & 1) * (2560u * 4u);
        uint32_t Bd = Bu + (uint32_t)(it & 1) * (2560u * 4u);
        const float* Bp = Bmat + (size_t)nb0 * KSP + kp;
#pragma unroll
        for (int p = 0; p < 2; p++) {
            int idx = tid + p * 256;
            int mm = idx >> 2, kq = idx & 3;
            CP16(Ad + (uint32_t)(mm * 20 + kq * 4) * 4u,
                 P + (size_t)(rb0 + mm) * stride + off + kq * 4);
            CP16(Bd + (uint32_t)(mm * 20 + kq * 4) * 4u,
                 Bp + (size_t)mm * KSP + kq * 4);
        }
        CP_COMMIT();
    };

    const int lane = tid & 31, w = tid >> 5;
    const int wm = (w >> 1) * 32, wn = (w & 1) * 64;
    const int g = lane >> 2, tg = lane & 3;

    float acc[2][8][4];
#pragma unroll
    for (int ma = 0; ma < 2; ma++)
#pragma unroll
        for (int na = 0; na < 8; na++)
#pragma unroll
            for (int q = 0; q < 4; q++) acc[ma][na][q] = 0.f;

    load_chunk(0);
    for (int it = 0; it < NIT; it++) {
        if (it + 1 < NIT) { load_chunk(it + 1); CP_WAIT1(); }
        else { CP_WAIT0(); }
        __syncthreads();
        const float* Ac = As + (it & 1) * 2560;
        const float* Bc = Bs + (it & 1) * 2560;
#pragma unroll
        for (int kk = 0; kk < 16; kk += 8) {
            uint32_t a[2][4], b[8][2];
#pragma unroll
            for (int ma = 0; ma < 2; ma++) {
                const float* ap = Ac + (wm + ma * 16 + g) * 20 + kk + tg;
                a[ma][0] = __float_as_uint(ap[0]);
                a[ma][1] = __float_as_uint(ap[160]);   // +8 rows
                a[ma][2] = __float_as_uint(ap[4]);     // +4 k
                a[ma][3] = __float_as_uint(ap[164]);
            }
#pragma unroll
            for (int na = 0; na < 8; na++) {
                const float* bp = Bc + (wn + na * 8 + g) * 20 + kk + tg;
                b[na][0] = __float_as_uint(bp[0]);
                b[na][1] = __float_as_uint(bp[4]);
            }
#pragma unroll
            for (int ma = 0; ma < 2; ma++)
#pragma unroll
                for (int na = 0; na < 8; na++)
                    asm volatile(
                        "mma.sync.aligned.m16n8k8.row.col.f32.tf32.tf32.f32 "
                        "{%0,%1,%2,%3}, {%4,%5,%6,%7}, {%8,%9}, {%0,%1,%2,%3};"
                        : "+f"(acc[ma][na][0]), "+f"(acc[ma][na][1]),
                          "+f"(acc[ma][na][2]), "+f"(acc[ma][na][3])
                        : "r"(a[ma][0]), "r"(a[ma][1]), "r"(a[ma][2]), "r"(a[ma][3]),
                          "r"(b[na][0]), "r"(b[na][1]));
        }
        __syncthreads();
    }

    // ---- epilogue: frags -> SMEM C tile [128][132] -> LSTM cell ----
    float* sC = sm;
#pragma unroll
    for (int ma = 0; ma < 2; ma++)
#pragma unroll
        for (int na = 0; na < 8; na++) {
            int r0 = wm + ma * 16 + g;
            int c0 = wn + na * 8 + tg * 2;
            *(float2*)&sC[r0 * 132 + c0]       = make_float2(acc[ma][na][0], acc[ma][na][1]);
            *(float2*)&sC[(r0 + 8) * 132 + c0] = make_float2(acc[ma][na][2], acc[ma][na][3]);
        }
    __syncthreads();

    const int row = tid >> 1, jh = tid & 1;
    const int grow = rb0 + row;
#pragma unroll
    for (int jj = 0; jj < 16; jj++) {
        int jl = jh * 16 + jj;
        float4 gt = *(const float4*)&sC[row * 132 + 4 * jl];
        int j = j0 + jl;
        int nc = nb0 + 4 * jl;
        float gi = gt.x + bias[nc + 0];
        float gf = gt.y + bias[nc + 1];
        float gg = gt.z + bias[nc + 2];
        float go = gt.w + bias[nc + 3];
        size_t ci = (size_t)grow * NH + j;
        float cn = fast_sigmoid(gf) * Cst[ci] + fast_sigmoid(gi) * fast_tanh(gg);
        float hn = fast_sigmoid(go) * fast_tanh(cn);
        Cst[ci] = cn;
        float hh = to_tf32(hn);
        HhiO[ci] = hh;
        HloO[ci] = to_tf32(hn - hh);
        if (is_dec) HfullO[ci] = hn;
        else g_enc[(size_t)grow * NT * NH + (size_t)t * NH + j] = hn;
    }
}

// ---------------- blend GEMM: C[M,256] = A[M,256] @ Bt ([k][n]) ----------------
__global__ __launch_bounds__(256) void ff_gemm_kernel(int mode) {
    __shared__ float As[16][68];
    __shared__ float Bs[16][128];
    const float* A  = mode ? g_hdfull : g_enc;
    const float* Bt = mode ? g_W2t : g_W1t;
    float* C        = mode ? g_blend2 : g_blend1;
    int tid = threadIdx.x;
    int tc = tid & 31, tr = tid >> 5;
    long rb0 = (long)blockIdx.y * 64;
    int nb0 = blockIdx.x * 128;

    float acc[8][4];
#pragma unroll
    for (int i = 0; i < 8; i++)
#pragma unroll
        for (int j2 = 0; j2 < 4; j2++) acc[i][j2] = 0.f;

    int am = tid >> 2, ak = (tid & 3) * 4;
    for (int k0 = 0; k0 < NH; k0 += 16) {
        long rowi = rb0 + am;
        float4 av = *(const float4*)&A[rowi * NH + k0 + ak];
        As[ak + 0][am] = av.x; As[ak + 1][am] = av.y;
        As[ak + 2][am] = av.z; As[ak + 3][am] = av.w;
#pragma unroll
        for (int p = 0; p < 2; p++) {
            int idx = tid + p * 256;
            int n = (idx & 31) * 4, k = idx >> 5;
            *(float4*)&Bs[k][n] = *(const float4*)&Bt[(k0 + k) * NW + nb0 + n];
        }
        __syncthreads();
#pragma unroll
        for (int k = 0; k < 16; k++) {
            float4 a0 = *(const float4*)&As[k][tr * 8];
            float4 a1 = *(const float4*)&As[k][tr * 8 + 4];
            float4 bv = *(const float4*)&Bs[k][tc * 4];
            float a[8] = {a0.x, a0.y, a0.z, a0.w, a1.x, a1.y, a1.z, a1.w};
            float b[4] = {bv.x, bv.y, bv.z, bv.w};
#pragma unroll
            for (int i = 0; i < 8; i++)
#pragma unroll
                for (int j2 = 0; j2 < 4; j2++) acc[i][j2] += a[i] * b[j2];
        }
        __syncthreads();
    }
#pragma unroll
    for (int i = 0; i < 8; i++) {
        long rowi = rb0 + tr * 8 + i;
        *(float4*)&C[rowi * NW + nb0 + tc * 4] =
            make_float4(acc[i][0], acc[i][1], acc[i][2], acc[i][3]);
    }
}

// ---------------- pointer attention step ----------------
__global__ __launch_bounds__(256) void attn_kernel(const float* __restrict__ targets,
                                                   const float* __restrict__ vt,
                                                   float* __restrict__ out, int step) {
    int b = blockIdx.x, tid = threadIdx.x;
    int lane = tid & 31, warp = tid >> 5;
    __shared__ float b2s[NW], vts[NW], sc[NT];
    __shared__ float red[8];
    __shared__ float mx_s, tot_s;
    __shared__ int sel_s;

    b2s[tid] = g_blend2[(long)b * NW + tid];
    vts[tid] = vt[tid];
    __syncthreads();

    for (int tt = warp; tt < NT; tt += 8) {
        const float* bl = &g_blend1[((long)b * NT + tt) * NW];
        float s = 0.f;
#pragma unroll
        for (int q = 0; q < NW / 32; q++) {
            int w = lane + q * 32;
            s += fast_tanh(bl[w] + b2s[w]) * vts[w];
        }
#pragma unroll
        for (int o = 16; o; o >>= 1) s += __shfl_down_sync(0xffffffffu, s, o);
        if (lane == 0) sc[tt] = g_mask[b * NT + tt] ? NEG_FILLF : s;
    }
    __syncthreads();

    if (tid == 0) {
        float mx = sc[0]; int mi = 0;
        for (int tt = 1; tt < NT; tt++)
            if (sc[tt] > mx) { mx = sc[tt]; mi = tt; }
        sel_s = mi; mx_s = mx;
    }
    __syncthreads();

    float e = (tid < NT) ? __expf(sc[tid] - mx_s) : 0.f;
    float s2 = e;
#pragma unroll
    for (int o = 16; o; o >>= 1) s2 += __shfl_down_sync(0xffffffffu, s2, o);
    if (lane == 0) red[warp] = s2;
    __syncthreads();
    if (tid == 0) {
        float tot = 0.f;
        for (int w = 0; w < 8; w++) tot += red[w];
        tot_s = tot;
    }
    __syncthreads();
    if (tid < NT) {
        float p = e / tot_s;
        if (p < PROB_MINF) p = PROB_MINF;
        out[((long)b * NT + step) * NT + tid] = p;
    }

    int sel = sel_s;
    if (tid == 0) g_mask[b * NT + sel] = 1;
    if (tid < ND) {
        float v = targets[((long)b * NT + sel) * ND + tid];
        float hv = to_tf32(v);
        g_dinhi[(long)b * ND + tid] = hv;
        g_dinlo[(long)b * ND + tid] = to_tf32(v - hv);
    }
}

// ---------------- launch ----------------
extern "C" void kernel_launch(void* const* d_in, const int* in_sizes, int n_in,
                              void* d_out, int out_size) {
    const float* targets = (const float*)d_in[0];
    const float* h0 = (const float*)d_in[1];
    const float* c0 = (const float*)d_in[2];
    float* out = (float*)d_out;

    cudaFuncSetAttribute(gemm_lstm_mma,
                         cudaFuncAttributeMaxDynamicSharedMemorySize, SMEM_DYN);

    init_kernel<<<(NB * NH) / 256, 256>>>(h0, c0);
    split_targets_kernel<<<(NB * NT * ND) / 256, 256>>>(targets);
    prep_kernel<<<(1024 * KCAT) / 256, 256>>>(
        (const float*)d_in[3], (const float*)d_in[4], (const float*)d_in[5],
        (const float*)d_in[6], (const float*)d_in[7], (const float*)d_in[8],
        (const float*)d_in[9], (const float*)d_in[10],
        (const float*)d_in[11], (const float*)d_in[12]);

    dim3 lgrid(8, 16);   // n-tiles x m-tiles
    for (int t = 0; t < NT; t++)
        gemm_lstm_mma<<<lgrid, 256, SMEM_DYN>>>(t, 0);

    ff_gemm_kernel<<<dim3(2, (NB * NT) / 64), 256>>>(0);   // blend1

    const float* vt = (const float*)d_in[13];
    for (int s = 0; s < NT; s++) {
        gemm_lstm_mma<<<lgrid, 256, SMEM_DYN>>>(s, 1);
        ff_gemm_kernel<<<dim3(2, NB / 64), 256>>>(1);      // blend2
        attn_kernel<<<NB, 256>>>(targets, vt, out, s);
    }
}

// round 13
// speedup vs baseline: 1.1708x; 1.1708x over previous
#include <cuda_runtime.h>
#include <cstdint>

#define NB 2048
#define NT 100
#define ND 128
#define NH 256
#define NW 256
#define KCAT 384
#define KSP 1152           // 3 * KCAT  (3xTF32)
#define NCHK 36            // KSP / 32
#define NEG_FILLF (-1.0e9f)
#define PROB_MINF (1e-9f)
#define SMEM_DYN 147456    // 4 stages x (A 128x36 + B 128x36) x 4B

// ---------------- static device scratch ----------------
__device__ float g_Benc[1024 * KSP];   // [n][k'] : [Whi | Wlo | Whi]
__device__ float g_Bdec[1024 * KSP];
__device__ float g_benc[1024], g_bdec[1024];
__device__ float g_W1t[NH * NW], g_W2t[NH * NW];
__device__ float g_thi[(size_t)NB * NT * ND];
__device__ float g_tlo[(size_t)NB * NT * ND];
__device__ float g_ehiA[NB * NH], g_eloA[NB * NH], g_ehiB[NB * NH], g_eloB[NB * NH];
__device__ float g_ce[NB * NH];
__device__ float g_dhiA[NB * NH], g_dloA[NB * NH], g_dhiB[NB * NH], g_dloB[NB * NH];
__device__ float g_cd[NB * NH];
__device__ float g_hdfull[NB * NH];
__device__ float g_dinhi[NB * ND], g_dinlo[NB * ND];
__device__ float g_enc[(size_t)NB * NT * NH];
__device__ float g_blend1[(size_t)NB * NT * NW];
__device__ float g_blend2[NB * NW];
__device__ int   g_mask[NB * NT];

// ---------------- helpers ----------------
__device__ __forceinline__ float fast_sigmoid(float x) {
    return __fdividef(1.f, 1.f + __expf(-x));
}
__device__ __forceinline__ float fast_tanh(float x) {
    return 2.f * __fdividef(1.f, 1.f + __expf(-2.f * x)) - 1.f;
}
__device__ __forceinline__ float to_tf32(float x) {
    uint32_t u; asm("cvt.rna.tf32.f32 %0, %1;" : "=r"(u) : "f"(x));
    return __uint_as_float(u);
}
__device__ __forceinline__ uint32_t smem_u32(const void* p) {
    uint32_t a;
    asm("{ .reg .u64 t; cvta.to.shared.u64 t, %1; cvt.u32.u64 %0, t; }" : "=r"(a) : "l"(p));
    return a;
}
#define CP16(dst, src) asm volatile("cp.async.cg.shared.global [%0], [%1], 16;" \
                                    :: "r"(dst), "l"(src) : "memory")
#define CP_COMMIT() asm volatile("cp.async.commit_group;" ::: "memory")
#define CP_WAIT2() asm volatile("cp.async.wait_group 2;" ::: "memory")

// ---------------- init ----------------
__global__ void init_kernel(const float* __restrict__ h0, const float* __restrict__ c0) {
    int i = blockIdx.x * blockDim.x + threadIdx.x;   // NB*NH
    g_ehiA[i] = 0.f; g_eloA[i] = 0.f; g_ce[i] = 0.f;
    float v = h0[i], hv = to_tf32(v);
    g_dhiA[i] = hv; g_dloA[i] = to_tf32(v - hv);
    g_cd[i] = c0[i];
    if (i < NB * ND) { g_dinhi[i] = 0.f; g_dinlo[i] = 0.f; }
    if (i < NB * NT) g_mask[i] = 0;
}

__global__ void split_targets_kernel(const float* __restrict__ tg) {
    size_t i = (size_t)blockIdx.x * blockDim.x + threadIdx.x;   // NB*NT*ND
    float v = tg[i], hv = to_tf32(v);
    g_thi[i] = hv; g_tlo[i] = to_tf32(v - hv);
}

// ---------------- prep: split + reorder weights into B' [n][1152] ----------------
__global__ void prep_kernel(const float* __restrict__ ewih, const float* __restrict__ ewhh,
                            const float* __restrict__ ebih, const float* __restrict__ ebhh,
                            const float* __restrict__ dwih, const float* __restrict__ dwhh,
                            const float* __restrict__ dbih, const float* __restrict__ dbhh,
                            const float* __restrict__ W1,   const float* __restrict__ W2) {
    int idx = blockIdx.x * blockDim.x + threadIdx.x;   // 1024*384
    int n = idx / KCAT, k = idx % KCAT;
    int j = n >> 2, g = n & 3, sr = g * NH + j;        // PyTorch gate-major row
    float ve = (k < ND) ? ewih[sr * ND + k] : ewhh[sr * NH + (k - ND)];
    float vd = (k < ND) ? dwih[sr * ND + k] : dwhh[sr * NH + (k - ND)];
    float ehv = to_tf32(ve), elv = to_tf32(ve - ehv);
    float dhv = to_tf32(vd), dlv = to_tf32(vd - dhv);
    size_t base = (size_t)n * KSP + k;
    g_Benc[base] = ehv; g_Benc[base + 384] = elv; g_Benc[base + 768] = ehv;
    g_Bdec[base] = dhv; g_Bdec[base + 384] = dlv; g_Bdec[base + 768] = dhv;
    if (idx < NH * NW) {
        int kk = idx >> 8, w = idx & 255;
        g_W1t[idx] = W1[w * NH + kk];
        g_W2t[idx] = W2[w * NH + kk];
    }
    if (idx < 1024) {
        int jb = idx >> 2, gb = idx & 3, srb = gb * NH + jb;
        g_benc[idx] = ebih[srb] + ebhh[srb];
        g_bdec[idx] = dbih[srb] + dbhh[srb];
    }
}

// ---------------- 3xTF32 mma.sync LSTM step, 4-stage pipelined ----------------
// C[2048,1024] = A'[2048,1152] @ B'[1152,1024]; CTA tile 128x128, 8 warps of 32x64.
// k32 chunks through a 4-stage cp.async ring (wait_group 2), register-double-buffered frags.
__global__ __launch_bounds__(256) void gemm_lstm_mma(int t, int is_dec) {
    extern __shared__ float sm[];
    const int tid = threadIdx.x;
    const int rb0 = blockIdx.y * 128;
    const int nb0 = blockIdx.x * 128;
    const int j0 = nb0 >> 2;

    const float *Xhi, *Xlo, *Hhi, *Hlo, *Bmat, *bias;
    float *HhiO, *HloO, *Cst, *HfullO;
    size_t xs; int xoff;
    if (is_dec) {
        Xhi = g_dinhi; Xlo = g_dinlo; xs = ND; xoff = 0;
        Hhi = (t & 1) ? g_dhiB : g_dhiA;  Hlo = (t & 1) ? g_dloB : g_dloA;
        HhiO = (t & 1) ? g_dhiA : g_dhiB; HloO = (t & 1) ? g_dloA : g_dloB;
        Cst = g_cd; Bmat = g_Bdec; bias = g_bdec; HfullO = g_hdfull;
    } else {
        Xhi = g_thi; Xlo = g_tlo; xs = (size_t)NT * ND; xoff = t * ND;
        Hhi = (t & 1) ? g_ehiB : g_ehiA;  Hlo = (t & 1) ? g_eloB : g_eloA;
        HhiO = (t & 1) ? g_ehiA : g_ehiB; HloO = (t & 1) ? g_eloA : g_eloB;
        Cst = g_ce; Bmat = g_Benc; bias = g_benc; HfullO = nullptr;
    }

    const uint32_t Au = smem_u32(sm);

    auto load_chunk = [&](int it) {
        int st = it & 3;
        int kp = it * 32;
        int term = kp / KCAT;                // 0: hi.Whi  1: hi.Wlo  2: lo.Whi
        int k = kp - term * KCAT;
        bool lo = (term == 2);
        const float* P; size_t stride; int off;
        if (k < ND) { P = lo ? Xlo : Xhi; stride = xs; off = xoff + k; }
        else        { P = lo ? Hlo : Hhi; stride = NH; off = k - ND; }
        uint32_t Ad = Au + (uint32_t)st * 36864u;
        uint32_t Bd = Ad + 18432u;
        const float* Bp = Bmat + (size_t)nb0 * KSP + kp;
#pragma unroll
        for (int p = 0; p < 4; p++) {
            int slot = tid + p * 256;
            int mm = slot >> 3, kq = slot & 7;
            CP16(Ad + (uint32_t)(mm * 36 + kq * 4) * 4u,
                 P + (size_t)(rb0 + mm) * stride + off + kq * 4);
            CP16(Bd + (uint32_t)(mm * 36 + kq * 4) * 4u,
                 Bp + (size_t)mm * KSP + kq * 4);
        }
        CP_COMMIT();
    };

    const int lane = tid & 31, w = tid >> 5;
    const int wm = (w >> 1) * 32, wn = (w & 1) * 64;
    const int g = lane >> 2, tg = lane & 3;

    float acc[2][8][4];
#pragma unroll
    for (int ma = 0; ma < 2; ma++)
#pragma unroll
        for (int na = 0; na < 8; na++)
#pragma unroll
            for (int q = 0; q < 4; q++) acc[ma][na][q] = 0.f;

    load_chunk(0); load_chunk(1); load_chunk(2);

    for (int it = 0; it < NCHK; it++) {
        CP_WAIT2();            // chunk `it` resident
        __syncthreads();       // also guards stage (it)&3 reuse by load at it+1
        if (it + 3 < NCHK) load_chunk(it + 3);
        else CP_COMMIT();      // keep wait level constant in the tail

        const float* Ac = sm + (it & 3) * 9216;
        const float* Bc = Ac + 4608;

        uint32_t fa[2][2][4], fb[2][8][2];
        auto loadfrag = [&](int buf, int kk) {
#pragma unroll
            for (int ma = 0; ma < 2; ma++) {
                const float* ap = Ac + (wm + ma * 16 + g) * 36 + kk + tg;
                fa[buf][ma][0] = __float_as_uint(ap[0]);
                fa[buf][ma][1] = __float_as_uint(ap[288]);   // +8 rows
                fa[buf][ma][2] = __float_as_uint(ap[4]);     // +4 k
                fa[buf][ma][3] = __float_as_uint(ap[292]);
            }
#pragma unroll
            for (int na = 0; na < 8; na++) {
                const float* bp = Bc + (wn + na * 8 + g) * 36 + kk + tg;
                fb[buf][na][0] = __float_as_uint(bp[0]);
                fb[buf][na][1] = __float_as_uint(bp[4]);
            }
        };

        loadfrag(0, 0);
#pragma unroll
        for (int h = 0; h < 4; h++) {
            if (h < 3) loadfrag((h + 1) & 1, (h + 1) * 8);
            const int buf = h & 1;
#pragma unroll
            for (int ma = 0; ma < 2; ma++)
#pragma unroll
                for (int na = 0; na < 8; na++)
                    asm volatile(
                        "mma.sync.aligned.m16n8k8.row.col.f32.tf32.tf32.f32 "
                        "{%0,%1,%2,%3}, {%4,%5,%6,%7}, {%8,%9}, {%0,%1,%2,%3};"
                        : "+f"(acc[ma][na][0]), "+f"(acc[ma][na][1]),
                          "+f"(acc[ma][na][2]), "+f"(acc[ma][na][3])
                        : "r"(fa[buf][ma][0]), "r"(fa[buf][ma][1]),
                          "r"(fa[buf][ma][2]), "r"(fa[buf][ma][3]),
                          "r"(fb[buf][na][0]), "r"(fb[buf][na][1]));
        }
    }

    // ---- epilogue: frags -> SMEM C tile [128][132] -> LSTM cell (coalesced) ----
    __syncthreads();
    float* sC = sm;
#pragma unroll
    for (int ma = 0; ma < 2; ma++)
#pragma unroll
        for (int na = 0; na < 8; na++) {
            int r0 = wm + ma * 16 + g;
            int c0 = wn + na * 8 + tg * 2;
            *(float2*)&sC[r0 * 132 + c0]       = make_float2(acc[ma][na][0], acc[ma][na][1]);
            *(float2*)&sC[(r0 + 8) * 132 + c0] = make_float2(acc[ma][na][2], acc[ma][na][3]);
        }
    __syncthreads();

    // lane = output column j (32 j's per tile), warp iterates 16 rows -> coalesced stores
    const int j = j0 + lane;
    const float4 bq = *(const float4*)&bias[nb0 + 4 * lane];
#pragma unroll
    for (int itr = 0; itr < 16; itr++) {
        int row = w * 16 + itr;
        int grow = rb0 + row;
        float4 gt = *(const float4*)&sC[row * 132 + 4 * lane];
        float gi = gt.x + bq.x;
        float gf = gt.y + bq.y;
        float gg = gt.z + bq.z;
        float go = gt.w + bq.w;
        size_t ci = (size_t)grow * NH + j;
        float cn = fast_sigmoid(gf) * Cst[ci] + fast_sigmoid(gi) * fast_tanh(gg);
        float hn = fast_sigmoid(go) * fast_tanh(cn);
        Cst[ci] = cn;
        float hh = to_tf32(hn);
        HhiO[ci] = hh;
        HloO[ci] = to_tf32(hn - hh);
        if (is_dec) HfullO[ci] = hn;
        else g_enc[(size_t)grow * NT * NH + (size_t)t * NH + j] = hn;
    }
}

// ---------------- blend GEMM: C[M,256] = A[M,256] @ Bt ([k][n]) ----------------
__global__ __launch_bounds__(256) void ff_gemm_kernel(int mode) {
    __shared__ float As[16][68];
    __shared__ float Bs[16][128];
    const float* A  = mode ? g_hdfull : g_enc;
    const float* Bt = mode ? g_W2t : g_W1t;
    float* C        = mode ? g_blend2 : g_blend1;
    int tid = threadIdx.x;
    int tc = tid & 31, tr = tid >> 5;
    long rb0 = (long)blockIdx.y * 64;
    int nb0 = blockIdx.x * 128;

    float acc[8][4];
#pragma unroll
    for (int i = 0; i < 8; i++)
#pragma unroll
        for (int j2 = 0; j2 < 4; j2++) acc[i][j2] = 0.f;

    int am = tid >> 2, ak = (tid & 3) * 4;
    for (int k0 = 0; k0 < NH; k0 += 16) {
        long rowi = rb0 + am;
        float4 av = *(const float4*)&A[rowi * NH + k0 + ak];
        As[ak + 0][am] = av.x; As[ak + 1][am] = av.y;
        As[ak + 2][am] = av.z; As[ak + 3][am] = av.w;
#pragma unroll
        for (int p = 0; p < 2; p++) {
            int idx = tid + p * 256;
            int n = (idx & 31) * 4, k = idx >> 5;
            *(float4*)&Bs[k][n] = *(const float4*)&Bt[(k0 + k) * NW + nb0 + n];
        }
        __syncthreads();
#pragma unroll
        for (int k = 0; k < 16; k++) {
            float4 a0 = *(const float4*)&As[k][tr * 8];
            float4 a1 = *(const float4*)&As[k][tr * 8 + 4];
            float4 bv = *(const float4*)&Bs[k][tc * 4];
            float a[8] = {a0.x, a0.y, a0.z, a0.w, a1.x, a1.y, a1.z, a1.w};
            float b[4] = {bv.x, bv.y, bv.z, bv.w};
#pragma unroll
            for (int i = 0; i < 8; i++)
#pragma unroll
                for (int j2 = 0; j2 < 4; j2++) acc[i][j2] += a[i] * b[j2];
        }
        __syncthreads();
    }
#pragma unroll
    for (int i = 0; i < 8; i++) {
        long rowi = rb0 + tr * 8 + i;
        *(float4*)&C[rowi * NW + nb0 + tc * 4] =
            make_float4(acc[i][0], acc[i][1], acc[i][2], acc[i][3]);
    }
}

// ---------------- pointer attention step ----------------
__global__ __launch_bounds__(256) void attn_kernel(const float* __restrict__ targets,
                                                   const float* __restrict__ vt,
                                                   float* __restrict__ out, int step) {
    int b = blockIdx.x, tid = threadIdx.x;
    int lane = tid & 31, warp = tid >> 5;
    __shared__ float b2s[NW], vts[NW], sc[NT];
    __shared__ float red[8];
    __shared__ float mx_s, tot_s;
    __shared__ int sel_s;

    b2s[tid] = g_blend2[(long)b * NW + tid];
    vts[tid] = vt[tid];
    __syncthreads();

    for (int tt = warp; tt < NT; tt += 8) {
        const float* bl = &g_blend1[((long)b * NT + tt) * NW];
        float s = 0.f;
#pragma unroll
        for (int q = 0; q < NW / 32; q++) {
            int w = lane + q * 32;
            s += fast_tanh(bl[w] + b2s[w]) * vts[w];
        }
#pragma unroll
        for (int o = 16; o; o >>= 1) s += __shfl_down_sync(0xffffffffu, s, o);
        if (lane == 0) sc[tt] = g_mask[b * NT + tt] ? NEG_FILLF : s;
    }
    __syncthreads();

    if (tid == 0) {
        float mx = sc[0]; int mi = 0;
        for (int tt = 1; tt < NT; tt++)
            if (sc[tt] > mx) { mx = sc[tt]; mi = tt; }
        sel_s = mi; mx_s = mx;
    }
    __syncthreads();

    float e = (tid < NT) ? __expf(sc[tid] - mx_s) : 0.f;
    float s2 = e;
#pragma unroll
    for (int o = 16; o; o >>= 1) s2 += __shfl_down_sync(0xffffffffu, s2, o);
    if (lane == 0) red[warp] = s2;
    __syncthreads();
    if (tid == 0) {
        float tot = 0.f;
        for (int w = 0; w < 8; w++) tot += red[w];
        tot_s = tot;
    }
    __syncthreads();
    if (tid < NT) {
        float p = e / tot_s;
        if (p < PROB_MINF) p = PROB_MINF;
        out[((long)b * NT + step) * NT + tid] = p;
    }

    int sel = sel_s;
    if (tid == 0) g_mask[b * NT + sel] = 1;
    if (tid < ND) {
        float v = targets[((long)b * NT + sel) * ND + tid];
        float hv = to_tf32(v);
        g_dinhi[(long)b * ND + tid] = hv;
        g_dinlo[(long)b * ND + tid] = to_tf32(v - hv);
    }
}

// ---------------- launch ----------------
extern "C" void kernel_launch(void* const* d_in, const int* in_sizes, int n_in,
                              void* d_out, int out_size) {
    const float* targets = (const float*)d_in[0];
    const float* h0 = (const float*)d_in[1];
    const float* c0 = (const float*)d_in[2];
    float* out = (float*)d_out;

    cudaFuncSetAttribute(gemm_lstm_mma,
                         cudaFuncAttributeMaxDynamicSharedMemorySize, SMEM_DYN);

    init_kernel<<<(NB * NH) / 256, 256>>>(h0, c0);
    split_targets_kernel<<<(NB * NT * ND) / 256, 256>>>(targets);
    prep_kernel<<<(1024 * KCAT) / 256, 256>>>(
        (const float*)d_in[3], (const float*)d_in[4], (const float*)d_in[5],
        (const float*)d_in[6], (const float*)d_in[7], (const float*)d_in[8],
        (const float*)d_in[9], (const float*)d_in[10],
        (const float*)d_in[11], (const float*)d_in[12]);

    dim3 lgrid(8, 16);   // n-tiles x m-tiles
    for (int t = 0; t < NT; t++)
        gemm_lstm_mma<<<lgrid, 256, SMEM_DYN>>>(t, 0);

    ff_gemm_kernel<<<dim3(2, (NB * NT) / 64), 256>>>(0);   // blend1

    const float* vt = (const float*)d_in[13];
    for (int s = 0; s < NT; s++) {
        gemm_lstm_mma<<<lgrid, 256, SMEM_DYN>>>(s, 1);
        ff_gemm_kernel<<<dim3(2, NB / 64), 256>>>(1);      // blend2
        attn_kernel<<<NB, 256>>>(targets, vt, out, s);
    }
}

// round 14
// speedup vs baseline: 1.2273x; 1.0483x over previous
#include <cuda_runtime.h>
#include <cstdint>

#define NB 2048
#define NT 100
#define ND 128
#define NH 256
#define NW 256
#define KH 768             // 3 * NH   (h-only 3xTF32)
#define NCHK_H 24          // KH / 32
#define KX 384             // 3 * ND
#define NCHK_X 12          // KX / 32
#define MX (NB * NT)       // 204800 rows of gx tables
#define NEG_FILLF (-1.0e9f)
#define PROB_MINF (1e-9f)
#define SMEM_DYN 147456    // 4 stages x (A 128x36 + B 128x36) x 4B

// ---------------- static device scratch ----------------
__device__ float g_Bhe[1024 * KH];     // [n][k'] : [Whh_hi | Whh_lo | Whh_hi]
__device__ float g_Bhd[1024 * KH];
__device__ float g_Bxe[1024 * KX];     // [n][k'] : [Wih_hi | Wih_lo | Wih_hi]
__device__ float g_Bxd[1024 * KX];
__device__ float g_benc[1024], g_bdec[1024];
__device__ float g_W1t[NH * NW], g_W2t[NH * NW];
__device__ float g_thi[(size_t)MX * ND];
__device__ float g_tlo[(size_t)MX * ND];
__device__ float g_gxe[(size_t)MX * 1024];   // enc x-gates table
__device__ float g_gxd[(size_t)MX * 1024];   // dec x-gates table
__device__ float g_ehiA[NB * NH], g_eloA[NB * NH], g_ehiB[NB * NH], g_eloB[NB * NH];
__device__ float g_ce[NB * NH];
__device__ float g_dhiA[NB * NH], g_dloA[NB * NH], g_dhiB[NB * NH], g_dloB[NB * NH];
__device__ float g_cd[NB * NH];
__device__ float g_hdfull[NB * NH];
__device__ int   g_sel[NB];
__device__ float g_enc[(size_t)NB * NT * NH];
__device__ float g_blend1[(size_t)NB * NT * NW];
__device__ float g_blend2[NB * NW];
__device__ int   g_mask[NB * NT];

// ---------------- helpers ----------------
__device__ __forceinline__ float fast_sigmoid(float x) {
    return __fdividef(1.f, 1.f + __expf(-x));
}
__device__ __forceinline__ float fast_tanh(float x) {
    return 2.f * __fdividef(1.f, 1.f + __expf(-2.f * x)) - 1.f;
}
__device__ __forceinline__ float to_tf32(float x) {
    uint32_t u; asm("cvt.rna.tf32.f32 %0, %1;" : "=r"(u) : "f"(x));
    return __uint_as_float(u);
}
__device__ __forceinline__ uint32_t smem_u32(const void* p) {
    uint32_t a;
    asm("{ .reg .u64 t; cvta.to.shared.u64 t, %1; cvt.u32.u64 %0, t; }" : "=r"(a) : "l"(p));
    return a;
}
#define CP16(dst, src) asm volatile("cp.async.cg.shared.global [%0], [%1], 16;" \
                                    :: "r"(dst), "l"(src) : "memory")
#define CP_COMMIT() asm volatile("cp.async.commit_group;" ::: "memory")
#define CP_WAIT2() asm volatile("cp.async.wait_group 2;" ::: "memory")
#define MMA_TF32(acc, fa, fb) \
    asm volatile("mma.sync.aligned.m16n8k8.row.col.f32.tf32.tf32.f32 " \
        "{%0,%1,%2,%3}, {%4,%5,%6,%7}, {%8,%9}, {%0,%1,%2,%3};" \
        : "+f"((acc)[0]), "+f"((acc)[1]), "+f"((acc)[2]), "+f"((acc)[3]) \
        : "r"((fa)[0]), "r"((fa)[1]), "r"((fa)[2]), "r"((fa)[3]), \
          "r"((fb)[0]), "r"((fb)[1]))

// ---------------- init ----------------
__global__ void init_kernel(const float* __restrict__ h0, const float* __restrict__ c0) {
    int i = blockIdx.x * blockDim.x + threadIdx.x;   // NB*NH
    g_ehiA[i] = 0.f; g_eloA[i] = 0.f; g_ce[i] = 0.f;
    float v = h0[i], hv = to_tf32(v);
    g_dhiA[i] = hv; g_dloA[i] = to_tf32(v - hv);
    g_cd[i] = c0[i];
    if (i < NB) g_sel[i] = -1;
    if (i < NB * NT) g_mask[i] = 0;
}

__global__ void split_targets_kernel(const float* __restrict__ tg) {
    size_t i = (size_t)blockIdx.x * blockDim.x + threadIdx.x;   // MX*ND
    float v = tg[i], hv = to_tf32(v);
    g_thi[i] = hv; g_tlo[i] = to_tf32(v - hv);
}

// ---------------- prep: split + reorder weights ----------------
__global__ void prep_kernel(const float* __restrict__ ewih, const float* __restrict__ ewhh,
                            const float* __restrict__ ebih, const float* __restrict__ ebhh,
                            const float* __restrict__ dwih, const float* __restrict__ dwhh,
                            const float* __restrict__ dbih, const float* __restrict__ dbhh,
                            const float* __restrict__ W1,   const float* __restrict__ W2) {
    int idx = blockIdx.x * blockDim.x + threadIdx.x;   // 1024*384
    int n = idx / 384, k = idx % 384;
    int j = n >> 2, g = n & 3, sr = g * NH + j;        // PyTorch gate-major row
    if (k < ND) {
        float ve = ewih[sr * ND + k], vd = dwih[sr * ND + k];
        float eh = to_tf32(ve), el = to_tf32(ve - eh);
        float dh = to_tf32(vd), dl = to_tf32(vd - dh);
        size_t b = (size_t)n * KX + k;
        g_Bxe[b] = eh; g_Bxe[b + 128] = el; g_Bxe[b + 256] = eh;
        g_Bxd[b] = dh; g_Bxd[b + 128] = dl; g_Bxd[b + 256] = dh;
    } else {
        int kh = k - ND;   // 0..255
        float ve = ewhh[sr * NH + kh], vd = dwhh[sr * NH + kh];
        float eh = to_tf32(ve), el = to_tf32(ve - eh);
        float dh = to_tf32(vd), dl = to_tf32(vd - dh);
        size_t b = (size_t)n * KH + kh;
        g_Bhe[b] = eh; g_Bhe[b + 256] = el; g_Bhe[b + 512] = eh;
        g_Bhd[b] = dh; g_Bhd[b + 256] = dl; g_Bhd[b + 512] = dh;
    }
    if (idx < NH * NW) {
        int kk = idx >> 8, w = idx & 255;
        g_W1t[idx] = W1[w * NH + kk];
        g_W2t[idx] = W2[w * NH + kk];
    }
    if (idx < 1024) {
        int jb = idx >> 2, gb = idx & 3, srb = gb * NH + jb;
        g_benc[idx] = ebih[srb] + ebhh[srb];
        g_bdec[idx] = dbih[srb] + dbhh[srb];
    }
}

// ---------------- gx tables: C[MX,1024] = split(targets) @ Wih'  ----------------
// 512 threads, 16 warps of 32x32, CTA tile 128x128, K=384 (12 k32 chunks).
__global__ __launch_bounds__(512) void gx_gemm(int is_dec) {
    extern __shared__ float sm[];
    const int tid = threadIdx.x;
    const size_t rb0 = (size_t)blockIdx.y * 128;
    const int nb0 = blockIdx.x * 128;
    const float* Bx = is_dec ? g_Bxd : g_Bxe;
    float* out = is_dec ? g_gxd : g_gxe;
    const uint32_t Au = smem_u32(sm);

    auto load_chunk = [&](int c) {
        int st = c & 3;
        int term = c >> 2, ko = (c & 3) * 32;
        const float* P = (term == 2) ? g_tlo : g_thi;
        uint32_t Ad = Au + (uint32_t)st * 36864u;
        uint32_t Bd = Ad + 18432u;
        const float* Bp = Bx + (size_t)nb0 * KX + c * 32;
#pragma unroll
        for (int p = 0; p < 2; p++) {
            int slot = tid + p * 512;
            int mm = slot >> 3, kq = slot & 7;
            CP16(Ad + (uint32_t)(mm * 36 + kq * 4) * 4u,
                 P + (rb0 + mm) * ND + ko + kq * 4);
            CP16(Bd + (uint32_t)(mm * 36 + kq * 4) * 4u,
                 Bp + (size_t)mm * KX + kq * 4);
        }
        CP_COMMIT();
    };

    const int lane = tid & 31, w = tid >> 5;
    const int wm = (w >> 2) * 32, wn = (w & 3) * 32;
    const int g = lane >> 2, tg = lane & 3;

    float acc[2][4][4];
#pragma unroll
    for (int ma = 0; ma < 2; ma++)
#pragma unroll
        for (int na = 0; na < 4; na++)
#pragma unroll
            for (int q = 0; q < 4; q++) acc[ma][na][q] = 0.f;

    load_chunk(0); load_chunk(1); load_chunk(2);
    for (int it = 0; it < NCHK_X; it++) {
        CP_WAIT2();
        __syncthreads();
        if (it + 3 < NCHK_X) load_chunk(it + 3);
        else CP_COMMIT();
        const float* Ac = sm + (it & 3) * 9216;
        const float* Bc = Ac + 4608;
        uint32_t fa[2][2][4], fb[2][4][2];
        auto loadfrag = [&](int buf, int kk) {
#pragma unroll
            for (int ma = 0; ma < 2; ma++) {
                const float* ap = Ac + (wm + ma * 16 + g) * 36 + kk + tg;
                fa[buf][ma][0] = __float_as_uint(ap[0]);
                fa[buf][ma][1] = __float_as_uint(ap[288]);
                fa[buf][ma][2] = __float_as_uint(ap[4]);
                fa[buf][ma][3] = __float_as_uint(ap[292]);
            }
#pragma unroll
            for (int na = 0; na < 4; na++) {
                const float* bp = Bc + (wn + na * 8 + g) * 36 + kk + tg;
                fb[buf][na][0] = __float_as_uint(bp[0]);
                fb[buf][na][1] = __float_as_uint(bp[4]);
            }
        };
        loadfrag(0, 0);
#pragma unroll
        for (int h = 0; h < 4; h++) {
            if (h < 3) loadfrag((h + 1) & 1, (h + 1) * 8);
            const int buf = h & 1;
#pragma unroll
            for (int ma = 0; ma < 2; ma++)
#pragma unroll
                for (int na = 0; na < 4; na++)
                    MMA_TF32(acc[ma][na], fa[buf][ma], fb[buf][na]);
        }
    }

    __syncthreads();
    float* sC = sm;
#pragma unroll
    for (int ma = 0; ma < 2; ma++)
#pragma unroll
        for (int na = 0; na < 4; na++) {
            int r0 = wm + ma * 16 + g;
            int c0 = wn + na * 8 + tg * 2;
            *(float2*)&sC[r0 * 132 + c0]       = make_float2(acc[ma][na][0], acc[ma][na][1]);
            *(float2*)&sC[(r0 + 8) * 132 + c0] = make_float2(acc[ma][na][2], acc[ma][na][3]);
        }
    __syncthreads();
#pragma unroll
    for (int itr = 0; itr < 8; itr++) {
        int row = w * 8 + itr;
        *(float4*)&out[(rb0 + row) * 1024 + nb0 + 4 * lane] =
            *(const float4*)&sC[row * 132 + 4 * lane];
    }
}

// ---------------- recurrent LSTM step: h-only 3xTF32 GEMM (K=768) + cell ----------------
__global__ __launch_bounds__(512) void gemm_lstm_mma(int t, int is_dec) {
    extern __shared__ float sm[];
    const int tid = threadIdx.x;
    const int rb0 = blockIdx.y * 128;
    const int nb0 = blockIdx.x * 128;
    const int j0 = nb0 >> 2;

    const float *Hhi, *Hlo, *Bh, *bias, *gxt;
    float *HhiO, *HloO, *Cst, *HfullO;
    if (is_dec) {
        Hhi = (t & 1) ? g_dhiB : g_dhiA;  Hlo = (t & 1) ? g_dloB : g_dloA;
        HhiO = (t & 1) ? g_dhiA : g_dhiB; HloO = (t & 1) ? g_dloA : g_dloB;
        Cst = g_cd; Bh = g_Bhd; bias = g_bdec; HfullO = g_hdfull; gxt = g_gxd;
    } else {
        Hhi = (t & 1) ? g_ehiB : g_ehiA;  Hlo = (t & 1) ? g_eloB : g_eloA;
        HhiO = (t & 1) ? g_ehiA : g_ehiB; HloO = (t & 1) ? g_eloA : g_eloB;
        Cst = g_ce; Bh = g_Bhe; bias = g_benc; HfullO = nullptr; gxt = g_gxe;
    }

    const uint32_t Au = smem_u32(sm);

    auto load_chunk = [&](int c) {
        int st = c & 3;
        int term = c >> 3, ko = (c & 7) * 32;
        const float* P = (term == 2) ? Hlo : Hhi;
        uint32_t Ad = Au + (uint32_t)st * 36864u;
        uint32_t Bd = Ad + 18432u;
        const float* Bp = Bh + (size_t)nb0 * KH + c * 32;
#pragma unroll
        for (int p = 0; p < 2; p++) {
            int slot = tid + p * 512;
            int mm = slot >> 3, kq = slot & 7;
            CP16(Ad + (uint32_t)(mm * 36 + kq * 4) * 4u,
                 P + (size_t)(rb0 + mm) * NH + ko + kq * 4);
            CP16(Bd + (uint32_t)(mm * 36 + kq * 4) * 4u,
                 Bp + (size_t)mm * KH + kq * 4);
        }
        CP_COMMIT();
    };

    const int lane = tid & 31, w = tid >> 5;
    const int wm = (w >> 2) * 32, wn = (w & 3) * 32;
    const int g = lane >> 2, tg = lane & 3;

    float acc[2][4][4];
#pragma unroll
    for (int ma = 0; ma < 2; ma++)
#pragma unroll
        for (int na = 0; na < 4; na++)
#pragma unroll
            for (int q = 0; q < 4; q++) acc[ma][na][q] = 0.f;

    load_chunk(0); load_chunk(1); load_chunk(2);
    for (int it = 0; it < NCHK_H; it++) {
        CP_WAIT2();
        __syncthreads();
        if (it + 3 < NCHK_H) load_chunk(it + 3);
        else CP_COMMIT();
        const float* Ac = sm + (it & 3) * 9216;
        const float* Bc = Ac + 4608;
        uint32_t fa[2][2][4], fb[2][4][2];
        auto loadfrag = [&](int buf, int kk) {
#pragma unroll
            for (int ma = 0; ma < 2; ma++) {
                const float* ap = Ac + (wm + ma * 16 + g) * 36 + kk + tg;
                fa[buf][ma][0] = __float_as_uint(ap[0]);
                fa[buf][ma][1] = __float_as_uint(ap[288]);
                fa[buf][ma][2] = __float_as_uint(ap[4]);
                fa[buf][ma][3] = __float_as_uint(ap[292]);
            }
#pragma unroll
            for (int na = 0; na < 4; na++) {
                const float* bp = Bc + (wn + na * 8 + g) * 36 + kk + tg;
                fb[buf][na][0] = __float_as_uint(bp[0]);
                fb[buf][na][1] = __float_as_uint(bp[4]);
            }
        };
        loadfrag(0, 0);
#pragma unroll
        for (int h = 0; h < 4; h++) {
            if (h < 3) loadfrag((h + 1) & 1, (h + 1) * 8);
            const int buf = h & 1;
#pragma unroll
            for (int ma = 0; ma < 2; ma++)
#pragma unroll
                for (int na = 0; na < 4; na++)
                    MMA_TF32(acc[ma][na], fa[buf][ma], fb[buf][na]);
        }
    }

    // ---- epilogue: frags -> SMEM C tile -> +gx +bias -> LSTM cell ----
    __syncthreads();
    float* sC = sm;
#pragma unroll
    for (int ma = 0; ma < 2; ma++)
#pragma unroll
        for (int na = 0; na < 4; na++) {
            int r0 = wm + ma * 16 + g;
            int c0 = wn + na * 8 + tg * 2;
            *(float2*)&sC[r0 * 132 + c0]       = make_float2(acc[ma][na][0], acc[ma][na][1]);
            *(float2*)&sC[(r0 + 8) * 132 + c0] = make_float2(acc[ma][na][2], acc[ma][na][3]);
        }
    __syncthreads();

    const int j = j0 + lane;
    const float4 bq = *(const float4*)&bias[nb0 + 4 * lane];
#pragma unroll
    for (int itr = 0; itr < 8; itr++) {
        int row = w * 8 + itr;
        int grow = rb0 + row;
        float4 gt = *(const float4*)&sC[row * 132 + 4 * lane];
        float4 gx = make_float4(0.f, 0.f, 0.f, 0.f);
        if (is_dec) {
            int sel = g_sel[grow];
            if (sel >= 0)
                gx = *(const float4*)&gxt[((size_t)grow * NT + sel) * 1024 + nb0 + 4 * lane];
        } else {
            gx = *(const float4*)&gxt[((size_t)grow * NT + t) * 1024 + nb0 + 4 * lane];
        }
        float gi = gt.x + gx.x + bq.x;
        float gf = gt.y + gx.y + bq.y;
        float gg = gt.z + gx.z + bq.z;
        float go = gt.w + gx.w + bq.w;
        size_t ci = (size_t)grow * NH + j;
        float cn = fast_sigmoid(gf) * Cst[ci] + fast_sigmoid(gi) * fast_tanh(gg);
        float hn = fast_sigmoid(go) * fast_tanh(cn);
        Cst[ci] = cn;
        float hh = to_tf32(hn);
        HhiO[ci] = hh;
        HloO[ci] = to_tf32(hn - hh);
        if (is_dec) HfullO[ci] = hn;
        else g_enc[(size_t)grow * NT * NH + (size_t)t * NH + j] = hn;
    }
}

// ---------------- blend GEMM: C[M,256] = A[M,256] @ Bt ([k][n]) ----------------
__global__ __launch_bounds__(256) void ff_gemm_kernel(int mode) {
    __shared__ float As[16][68];
    __shared__ float Bs[16][128];
    const float* A  = mode ? g_hdfull : g_enc;
    const float* Bt = mode ? g_W2t : g_W1t;
    float* C        = mode ? g_blend2 : g_blend1;
    int tid = threadIdx.x;
    int tc = tid & 31, tr = tid >> 5;
    long rb0 = (long)blockIdx.y * 64;
    int nb0 = blockIdx.x * 128;

    float acc[8][4];
#pragma unroll
    for (int i = 0; i < 8; i++)
#pragma unroll
        for (int j2 = 0; j2 < 4; j2++) acc[i][j2] = 0.f;

    int am = tid >> 2, ak = (tid & 3) * 4;
    for (int k0 = 0; k0 < NH; k0 += 16) {
        long rowi = rb0 + am;
        float4 av = *(const float4*)&A[rowi * NH + k0 + ak];
        As[ak + 0][am] = av.x; As[ak + 1][am] = av.y;
        As[ak + 2][am] = av.z; As[ak + 3][am] = av.w;
#pragma unroll
        for (int p = 0; p < 2; p++) {
            int idx = tid + p * 256;
            int n = (idx & 31) * 4, k = idx >> 5;
            *(float4*)&Bs[k][n] = *(const float4*)&Bt[(k0 + k) * NW + nb0 + n];
        }
        __syncthreads();
#pragma unroll
        for (int k = 0; k < 16; k++) {
            float4 a0 = *(const float4*)&As[k][tr * 8];
            float4 a1 = *(const float4*)&As[k][tr * 8 + 4];
            float4 bv = *(const float4*)&Bs[k][tc * 4];
            float a[8] = {a0.x, a0.y, a0.z, a0.w, a1.x, a1.y, a1.z, a1.w};
            float b[4] = {bv.x, bv.y, bv.z, bv.w};
#pragma unroll
            for (int i = 0; i < 8; i++)
#pragma unroll
                for (int j2 = 0; j2 < 4; j2++) acc[i][j2] += a[i] * b[j2];
        }
        __syncthreads();
    }
#pragma unroll
    for (int i = 0; i < 8; i++) {
        long rowi = rb0 + tr * 8 + i;
        *(float4*)&C[rowi * NW + nb0 + tc * 4] =
            make_float4(acc[i][0], acc[i][1], acc[i][2], acc[i][3]);
    }
}

// ---------------- pointer attention step ----------------
__global__ __launch_bounds__(256) void attn_kernel(const float* __restrict__ vt,
                                                   float* __restrict__ out, int step) {
    int b = blockIdx.x, tid = threadIdx.x;
    int lane = tid & 31, warp = tid >> 5;
    __shared__ float b2s[NW], vts[NW], sc[NT];
    __shared__ float red[8];
    __shared__ float mx_s, tot_s;
    __shared__ int sel_s;

    b2s[tid] = g_blend2[(long)b * NW + tid];
    vts[tid] = vt[tid];
    __syncthreads();

    for (int tt = warp; tt < NT; tt += 8) {
        const float* bl = &g_blend1[((long)b * NT + tt) * NW];
        float s = 0.f;
#pragma unroll
        for (int q = 0; q < NW / 32; q++) {
            int w = lane + q * 32;
            s += fast_tanh(bl[w] + b2s[w]) * vts[w];
        }
#pragma unroll
        for (int o = 16; o; o >>= 1) s += __shfl_down_sync(0xffffffffu, s, o);
        if (lane == 0) sc[tt] = g_mask[b * NT + tt] ? NEG_FILLF : s;
    }
    __syncthreads();

    if (tid == 0) {
        float mx = sc[0]; int mi = 0;
        for (int tt = 1; tt < NT; tt++)
            if (sc[tt] > mx) { mx = sc[tt]; mi = tt; }
        sel_s = mi; mx_s = mx;
    }
    __syncthreads();

    float e = (tid < NT) ? __expf(sc[tid] - mx_s) : 0.f;
    float s2 = e;
#pragma unroll
    for (int o = 16; o; o >>= 1) s2 += __shfl_down_sync(0xffffffffu, s2, o);
    if (lane == 0) red[warp] = s2;
    __syncthreads();
    if (tid == 0) {
        float tot = 0.f;
        for (int w = 0; w < 8; w++) tot += red[w];
        tot_s = tot;
    }
    __syncthreads();
    if (tid < NT) {
        float p = e / tot_s;
        if (p < PROB_MINF) p = PROB_MINF;
        out[((long)b * NT + step) * NT + tid] = p;
    }

    if (tid == 0) {
        g_mask[b * NT + sel_s] = 1;
        g_sel[b] = sel_s;          // next decoder step gathers gxd[b, sel]
    }
}

// ---------------- launch ----------------
extern "C" void kernel_launch(void* const* d_in, const int* in_sizes, int n_in,
                              void* d_out, int out_size) {
    const float* targets = (const float*)d_in[0];
    const float* h0 = (const float*)d_in[1];
    const float* c0 = (const float*)d_in[2];
    float* out = (float*)d_out;

    cudaFuncSetAttribute(gemm_lstm_mma,
                         cudaFuncAttributeMaxDynamicSharedMemorySize, SMEM_DYN);
    cudaFuncSetAttribute(gx_gemm,
                         cudaFuncAttributeMaxDynamicSharedMemorySize, SMEM_DYN);

    init_kernel<<<(NB * NH) / 256, 256>>>(h0, c0);
    split_targets_kernel<<<((size_t)MX * ND) / 256, 256>>>(targets);
    prep_kernel<<<(1024 * 384) / 256, 256>>>(
        (const float*)d_in[3], (const float*)d_in[4], (const float*)d_in[5],
        (const float*)d_in[6], (const float*)d_in[7], (const float*)d_in[8],
        (const float*)d_in[9], (const float*)d_in[10],
        (const float*)d_in[11], (const float*)d_in[12]);

    dim3 xgrid(8, MX / 128);   // (8, 1600)
    gx_gemm<<<xgrid, 512, SMEM_DYN>>>(0);
    gx_gemm<<<xgrid, 512, SMEM_DYN>>>(1);

    dim3 lgrid(8, 16);
    for (int t = 0; t < NT; t++)
        gemm_lstm_mma<<<lgrid, 512, SMEM_DYN>>>(t, 0);

    ff_gemm_kernel<<<dim3(2, (NB * NT) / 64), 256>>>(0);   // blend1

    const float* vt = (const float*)d_in[13];
    for (int s = 0; s < NT; s++) {
        gemm_lstm_mma<<<lgrid, 512, SMEM_DYN>>>(s, 1);
        ff_gemm_kernel<<<dim3(2, NB / 64), 256>>>(1);      // blend2
        attn_kernel<<<NB, 256>>>(vt, out, s);
    }
}